// round 10
// baseline (speedup 1.0000x reference)
#include <cuda_runtime.h>
#include <math.h>

#define BATCH 32
#define SEQ   4096
#define NTOK  (BATCH*SEQ)      // 131072
#define AD    64
#define DCODE 256
#define KCODES 512

// ---------------- packed dual-fp32 FMA (bit-identical per-lane IEEE fma) ----
__device__ __forceinline__ void ffma2(float2& acc, float2 a, float2 b)
{
    unsigned long long A = *reinterpret_cast<unsigned long long*>(&a);
    unsigned long long B = *reinterpret_cast<unsigned long long*>(&b);
    unsigned long long C = *reinterpret_cast<unsigned long long*>(&acc);
    asm("fma.rn.f32x2 %0, %1, %2, %0;" : "+l"(C) : "l"(A), "l"(B));
    acc = *reinterpret_cast<float2*>(&C);
}

// ---------------- warp row-reduce for sum(x^2) (frozen since R7) ------------
__device__ __forceinline__ float warp_sumsq_256(const float* __restrict__ row, int lane)
{
    float ax = 0.f, ay = 0.f;
#pragma unroll
    for (int i = 0; i < 4; i++) {
        float v0 = row[64*i + 2*lane + 0];
        float v1 = row[64*i + 2*lane + 1];
        ax = __fadd_rn(ax, __fmul_rn(v0, v0));
        ay = __fadd_rn(ay, __fmul_rn(v1, v1));
    }
    float s = __fadd_rn(ax, ay);
#pragma unroll
    for (int off = 16; off > 0; off >>= 1) {
        float o = __shfl_down_sync(0xffffffffu, s, off);
        s = __fadd_rn(s, o);
    }
    return s;   // valid in lane 0
}

// ---------------- scratch (__device__ globals: allocation-free) -------------
__device__ float g_bufA[NTOK*256];   // widest intermediate (z_e)
__device__ float g_bufB[NTOK*128];
__device__ float g_W_e0[BATCH*64*128];
__device__ float g_W_e1[BATCH*128*64];
__device__ float g_W_e2[BATCH*256*128];
__device__ float g_W_d0[BATCH*128*256];
__device__ float g_W_d1[BATCH*64*128];
__device__ float g_W_d2[BATCH*128*64];
__device__ int          g_idx[NTOK];
__device__ float        g_cnorm[KCODES];
__device__ unsigned int g_hist[KCODES];
__device__ double       g_sumsq;

// ---------------- stats reset (graph is replayed; must rezero) -------------
__global__ void zero_stats_k()
{
    int t = threadIdx.x;
    if (t < KCODES) g_hist[t] = 0u;
    if (t == 0)     g_sumsq = 0.0;
}

// ---------------- per-batch weight materialization (frozen since R3) --------
__global__ __launch_bounds__(256) void build_w_k(
    const float* __restrict__ bw, const float* __restrict__ aw,
    const float* __restrict__ ab, const float* __restrict__ adapt,
    float* __restrict__ Wout, int E)
{
    __shared__ float ad[BATCH*AD];
    for (int i = threadIdx.x; i < BATCH*AD; i += blockDim.x) ad[i] = adapt[i];
    __syncthreads();

    int e = blockIdx.x * blockDim.x + threadIdx.x;
    if (e >= E) return;

    float awr[AD];
#pragma unroll
    for (int d = 0; d < AD; d += 4) {
        float4 v = *reinterpret_cast<const float4*>(aw + (long)e*AD + d);
        awr[d] = v.x; awr[d+1] = v.y; awr[d+2] = v.z; awr[d+3] = v.w;
    }
    const float base = bw[e];
    const float abv  = ab[e];
    for (int b = 0; b < BATCH; b++) {
        float acc = 0.f;
#pragma unroll
        for (int d = 0; d < AD; d++) acc = fmaf(ad[b*AD + d], awr[d], acc);
        acc = __fadd_rn(acc, abv);
        Wout[(long)b*E + e] = __fadd_rn(base, acc);
    }
}

// ---------------- codebook squared norms (frozen since R7) ------------------
__global__ __launch_bounds__(256) void cnorm_k(const float* __restrict__ CB)
{
    int warp = (blockIdx.x * blockDim.x + threadIdx.x) >> 5;  // = code index
    int lane = threadIdx.x & 31;
    if (warp < KCODES) {
        float s = warp_sumsq_256(CB + (long)warp * DCODE, lane);
        if (lane == 0) g_cnorm[warp] = s;
    }
}

// ---------------- liquid layer: batched GEMM + bias + activation (frozen) ---
template<int IN, int OUT, int ACT>
__global__ __launch_bounds__(256) void liquid_gemm_k(
    const float* __restrict__ X, const float* __restrict__ Wall,
    const float* __restrict__ bb, float* __restrict__ Y)
{
    const int b  = blockIdx.z;
    const int m0 = blockIdx.x * 64;
    const int n0 = blockIdx.y * 64;
    const float* Xb = X    + ((long)b*SEQ + m0) * IN;
    const float* Wb = Wall + (long)b*OUT*IN + (long)n0*IN;
    float*       Yb = Y    + ((long)b*SEQ + m0) * OUT + n0;

    __shared__ float As[16][68];
    __shared__ float Bs[16][68];

    const int tid  = threadIdx.x;
    const int lrow = tid >> 2;
    const int lk4  = (tid & 3) * 4;
    const int ty   = tid >> 4;
    const int tx   = tid & 15;

    float2 acc2[4][2];
#pragma unroll
    for (int i = 0; i < 4; i++) { acc2[i][0] = make_float2(0.f,0.f); acc2[i][1] = make_float2(0.f,0.f); }

    for (int k0 = 0; k0 < IN; k0 += 16) {
        float4 av = *reinterpret_cast<const float4*>(Xb + (long)lrow*IN + k0 + lk4);
        float4 bv = *reinterpret_cast<const float4*>(Wb + (long)lrow*IN + k0 + lk4);
        __syncthreads();
        As[lk4+0][lrow] = av.x; As[lk4+1][lrow] = av.y;
        As[lk4+2][lrow] = av.z; As[lk4+3][lrow] = av.w;
        Bs[lk4+0][lrow] = bv.x; Bs[lk4+1][lrow] = bv.y;
        Bs[lk4+2][lrow] = bv.z; Bs[lk4+3][lrow] = bv.w;
        __syncthreads();
#pragma unroll
        for (int k = 0; k < 16; k++) {
            float4 a = *reinterpret_cast<const float4*>(&As[k][ty*4]);
            float4 q = *reinterpret_cast<const float4*>(&Bs[k][tx*4]);
            float2 b0 = make_float2(q.x, q.y);
            float2 b1 = make_float2(q.z, q.w);
            float2 a0 = make_float2(a.x, a.x);
            float2 a1 = make_float2(a.y, a.y);
            float2 a2 = make_float2(a.z, a.z);
            float2 a3 = make_float2(a.w, a.w);
            ffma2(acc2[0][0], a0, b0); ffma2(acc2[0][1], a0, b1);
            ffma2(acc2[1][0], a1, b0); ffma2(acc2[1][1], a1, b1);
            ffma2(acc2[2][0], a2, b0); ffma2(acc2[2][1], a2, b1);
            ffma2(acc2[3][0], a3, b0); ffma2(acc2[3][1], a3, b1);
        }
    }

    float bias[4];
#pragma unroll
    for (int j = 0; j < 4; j++) bias[j] = bb[n0 + tx*4 + j];

#pragma unroll
    for (int i = 0; i < 4; i++) {
        const int m = ty*4 + i;
        float accv[4] = { acc2[i][0].x, acc2[i][0].y, acc2[i][1].x, acc2[i][1].y };
#pragma unroll
        for (int j = 0; j < 4; j++) {
            float v = __fadd_rn(accv[j], bias[j]);
            if (ACT == 1) v = fmaxf(v, 0.f);
            if (ACT == 2) v = 1.f / (1.f + expf(-v));
            Yb[(long)m*OUT + tx*4 + j] = v;
        }
    }
}

// ---------------- VQ argmin --------------------------------------------------
// R10 CHANGE (chain redraw, Eigen/LLVM 4-acc candidate): dot accumulated in
// FOUR interleaved FMA chains by k mod 4 (latency-hiding unroll pattern),
// folded sequentially: dot = ((c0+c1)+c2)+c3, each fold __fadd_rn.
// Everything else (zn/cn, epilogue rounding, tie-break) bit-frozen.
__global__ __launch_bounds__(256) void vq_argmin_k(
    const float* __restrict__ Z, const float* __restrict__ CB)
{
    extern __shared__ float sm[];
    float (*Zs)[260] = (float (*)[260]) sm;                       // 64 x 260
    float (*Bs)[68]  = (float (*)[68])  (sm + 64*260);            // 16 x 68
    float (*rv)[17]  = (float (*)[17])  (sm + 64*260 + 16*68);    // 64 x 17
    int   (*ri)[17]  = (int   (*)[17])  (sm + 64*260 + 16*68 + 64*17);
    float *zn_s      = (float*)         (sm + 64*260 + 16*68 + 64*17 + 64*17);

    const int m0  = blockIdx.x * 64;
    const int tid = threadIdx.x;

    for (int i = tid; i < 64*64; i += 256) {
        int m = i >> 6;
        int q = (i & 63) * 4;
        float4 v = *reinterpret_cast<const float4*>(Z + (long)(m0 + m)*DCODE + q);
        *reinterpret_cast<float4*>(&Zs[m][q]) = v;
    }
    __syncthreads();

    {
        const int warp = tid >> 5;
        const int lane = tid & 31;
        for (int j = 0; j < 8; j++) {
            int tok = warp * 8 + j;
            float s = warp_sumsq_256(&Zs[tok][0], lane);
            if (lane == 0) zn_s[tok] = s;
        }
    }
    __syncthreads();

    const int lrow = tid >> 2;
    const int lk4  = (tid & 3) * 4;
    const int ty   = tid >> 4;
    const int tx   = tid & 15;

    float zn[4];
#pragma unroll
    for (int i = 0; i < 4; i++) zn[i] = zn_s[ty*4 + i];

    float bestv[4];
    int   besti[4];
#pragma unroll
    for (int i = 0; i < 4; i++) { bestv[i] = 3.4e38f; besti[i] = 0; }

    for (int n0 = 0; n0 < KCODES; n0 += 64) {
        // Four interleaved accumulator sets: phase p = k mod 4.
        float2 acc[4][4][2];   // [phase][i][h]
#pragma unroll
        for (int p = 0; p < 4; p++)
#pragma unroll
            for (int i = 0; i < 4; i++) {
                acc[p][i][0] = make_float2(0.f,0.f);
                acc[p][i][1] = make_float2(0.f,0.f);
            }

        for (int k0 = 0; k0 < DCODE; k0 += 16) {
            float4 bv = *reinterpret_cast<const float4*>(
                CB + (long)(n0 + lrow)*DCODE + k0 + lk4);
            __syncthreads();
            Bs[lk4+0][lrow] = bv.x; Bs[lk4+1][lrow] = bv.y;
            Bs[lk4+2][lrow] = bv.z; Bs[lk4+3][lrow] = bv.w;
            __syncthreads();
#pragma unroll
            for (int k = 0; k < 16; k++) {
                const int p = k & 3;
                float4 q = *reinterpret_cast<const float4*>(&Bs[k][tx*4]);
                float2 b0 = make_float2(q.x, q.y);
                float2 b1 = make_float2(q.z, q.w);
                float2 a0 = make_float2(Zs[ty*4+0][k0+k], Zs[ty*4+0][k0+k]);
                float2 a1 = make_float2(Zs[ty*4+1][k0+k], Zs[ty*4+1][k0+k]);
                float2 a2 = make_float2(Zs[ty*4+2][k0+k], Zs[ty*4+2][k0+k]);
                float2 a3 = make_float2(Zs[ty*4+3][k0+k], Zs[ty*4+3][k0+k]);
                ffma2(acc[p][0][0], a0, b0); ffma2(acc[p][0][1], a0, b1);
                ffma2(acc[p][1][0], a1, b0); ffma2(acc[p][1][1], a1, b1);
                ffma2(acc[p][2][0], a2, b0); ffma2(acc[p][2][1], a2, b1);
                ffma2(acc[p][3][0], a3, b0); ffma2(acc[p][3][1], a3, b1);
            }
        }
#pragma unroll
        for (int j = 0; j < 4; j++) {
            const int code = n0 + tx*4 + j;
            const float cn = g_cnorm[code];
#pragma unroll
            for (int i = 0; i < 4; i++) {
                const int h = j >> 1;
                float c0 = (j & 1) ? acc[0][i][h].y : acc[0][i][h].x;
                float c1 = (j & 1) ? acc[1][i][h].y : acc[1][i][h].x;
                float c2 = (j & 1) ? acc[2][i][h].y : acc[2][i][h].x;
                float c3 = (j & 1) ? acc[3][i][h].y : acc[3][i][h].x;
                float dot = __fadd_rn(__fadd_rn(__fadd_rn(c0, c1), c2), c3);
                float t = __fadd_rn(zn[i], cn);                    // fl(zn + cn)
                float s = __fadd_rn(t, -__fmul_rn(2.f, dot));      // fl(t - 2*dot)
                if (s < bestv[i]) { bestv[i] = s; besti[i] = code; }
            }
        }
    }

    __syncthreads();
#pragma unroll
    for (int i = 0; i < 4; i++) {
        rv[ty*4 + i][tx] = bestv[i];
        ri[ty*4 + i][tx] = besti[i];
    }
    __syncthreads();

    if (tid < 64) {
        float bv = rv[tid][0]; int bi = ri[tid][0];
#pragma unroll
        for (int x = 1; x < 16; x++) {
            float v = rv[tid][x]; int ii = ri[tid][x];
            if (v < bv || (v == bv && ii < bi)) { bv = v; bi = ii; }
        }
        g_idx[m0 + tid] = bi;
    }
}

// ---------------- gather z_q (straight-through) + loss + histogram ----------
__global__ __launch_bounds__(256) void vq_gather_k(
    const float* __restrict__ Z, const float* __restrict__ CB,
    float* __restrict__ zq_out)
{
    __shared__ unsigned int hist_s[KCODES];
    __shared__ float ws[8];
    for (int i = threadIdx.x; i < KCODES; i += blockDim.x) hist_s[i] = 0u;
    __syncthreads();

    float lsum = 0.f;
    const int total  = NTOK * DCODE;
    const int stride = gridDim.x * blockDim.x;
    for (int e = blockIdx.x * blockDim.x + threadIdx.x; e < total; e += stride) {
        int token = e >> 8;
        int d     = e & 255;
        int idx   = g_idx[token];
        float q   = CB[(long)idx*DCODE + d];
        float z   = Z[e];
        float diff = __fadd_rn(q, -z);          // fl(q - z)
        lsum += diff * diff;
        zq_out[e] = __fadd_rn(z, diff);         // quantized_st = fl(z + fl(q - z))
        if (d == 0) atomicAdd(&hist_s[idx], 1u);
    }

#pragma unroll
    for (int o = 16; o > 0; o >>= 1) lsum += __shfl_xor_sync(0xffffffffu, lsum, o);
    if ((threadIdx.x & 31) == 0) ws[threadIdx.x >> 5] = lsum;
    __syncthreads();
    if (threadIdx.x == 0) {
        float s = 0.f;
#pragma unroll
        for (int w = 0; w < 8; w++) s += ws[w];
        atomicAdd(&g_sumsq, (double)s);
    }
    for (int i = threadIdx.x; i < KCODES; i += blockDim.x)
        if (hist_s[i]) atomicAdd(&g_hist[i], hist_s[i]);
}

// ---------------- scalars: vq_loss, perplexity ------------------------------
__global__ void finalize_k(float* __restrict__ scalars)
{
    if (threadIdx.x == 0 && blockIdx.x == 0) {
        double mse = g_sumsq / (double)((long)NTOK * DCODE);
        scalars[0] = (float)(mse * 1.25);
        double H = 0.0;
        for (int k = 0; k < KCODES; k++) {
            double p = (double)g_hist[k] / (double)NTOK;
            H -= p * log(p + 1e-10);
        }
        scalars[1] = (float)exp(H);
    }
}

// ---------------- launch --------------------------------------------------
static float* symaddr(const void* sym)
{
    void* p = nullptr;
    cudaGetSymbolAddress(&p, sym);
    return (float*)p;
}

extern "C" void kernel_launch(void* const* d_in, const int* in_sizes, int n_in,
                              void* d_out, int out_size)
{
    (void)in_sizes; (void)n_in; (void)out_size;

    const float* x        = (const float*)d_in[0];
    const float* adapt    = (const float*)d_in[1];
    const float* e0_bw = (const float*)d_in[2],  *e0_bb = (const float*)d_in[3],
               * e0_aw = (const float*)d_in[4],  *e0_ab = (const float*)d_in[5];
    const float* e1_bw = (const float*)d_in[6],  *e1_bb = (const float*)d_in[7],
               * e1_aw = (const float*)d_in[8],  *e1_ab = (const float*)d_in[9];
    const float* e2_bw = (const float*)d_in[10], *e2_bb = (const float*)d_in[11],
               * e2_aw = (const float*)d_in[12], *e2_ab = (const float*)d_in[13];
    const float* d0_bw = (const float*)d_in[14], *d0_bb = (const float*)d_in[15],
               * d0_aw = (const float*)d_in[16], *d0_ab = (const float*)d_in[17];
    const float* d1_bw = (const float*)d_in[18], *d1_bb = (const float*)d_in[19],
               * d1_aw = (const float*)d_in[20], *d1_ab = (const float*)d_in[21];
    const float* d2_bw = (const float*)d_in[22], *d2_bb = (const float*)d_in[23],
               * d2_aw = (const float*)d_in[24], *d2_ab = (const float*)d_in[25];
    const float* codebook = (const float*)d_in[26];

    float* out     = (float*)d_out;
    float* zq      = out;                       // [32,4096,256]
    float* scalars = out + (long)NTOK * DCODE;  // loss, perplexity
    float* recon   = scalars + 2;               // [32,4096,128]

    float* bufA = symaddr(g_bufA);
    float* bufB = symaddr(g_bufB);
    float* W_e0 = symaddr(g_W_e0);
    float* W_e1 = symaddr(g_W_e1);
    float* W_e2 = symaddr(g_W_e2);
    float* W_d0 = symaddr(g_W_d0);
    float* W_d1 = symaddr(g_W_d1);
    float* W_d2 = symaddr(g_W_d2);

    const dim3 blk(256);

    zero_stats_k<<<1, 512>>>();

    build_w_k<<<(64*128 + 255)/256, blk>>>(e0_bw, e0_aw, e0_ab, adapt, W_e0, 64*128);
    build_w_k<<<(128*64 + 255)/256, blk>>>(e1_bw, e1_aw, e1_ab, adapt, W_e1, 128*64);
    build_w_k<<<(256*128 + 255)/256, blk>>>(e2_bw, e2_aw, e2_ab, adapt, W_e2, 256*128);
    build_w_k<<<(128*256 + 255)/256, blk>>>(d0_bw, d0_aw, d0_ab, adapt, W_d0, 128*256);
    build_w_k<<<(64*128 + 255)/256, blk>>>(d1_bw, d1_aw, d1_ab, adapt, W_d1, 64*128);
    build_w_k<<<(128*64 + 255)/256, blk>>>(d2_bw, d2_aw, d2_ab, adapt, W_d2, 128*64);

    cnorm_k<<<64, blk>>>(codebook);   // 512 warps = 512 codes

    // encoder
    liquid_gemm_k<128,  64, 1><<<dim3(64, 1, BATCH), blk>>>(x,    W_e0, e0_bb, bufA);
    liquid_gemm_k< 64, 128, 1><<<dim3(64, 2, BATCH), blk>>>(bufA, W_e1, e1_bb, bufB);
    liquid_gemm_k<128, 256, 0><<<dim3(64, 4, BATCH), blk>>>(bufB, W_e2, e2_bb, bufA);

    // vector quantization
    const int vq_smem = (64*260 + 16*68 + 64*17 + 64*17 + 64) * (int)sizeof(float);
    cudaFuncSetAttribute(vq_argmin_k, cudaFuncAttributeMaxDynamicSharedMemorySize, vq_smem);
    vq_argmin_k<<<NTOK/64, blk, vq_smem>>>(bufA, codebook);
    vq_gather_k<<<1024, blk>>>(bufA, codebook, zq);

    // decoder
    liquid_gemm_k<256, 128, 1><<<dim3(64, 2, BATCH), blk>>>(zq,   W_d0, d0_bb, bufB);
    liquid_gemm_k<128,  64, 1><<<dim3(64, 1, BATCH), blk>>>(bufB, W_d1, d1_bb, bufA);
    liquid_gemm_k< 64, 128, 2><<<dim3(64, 2, BATCH), blk>>>(bufA, W_d2, d2_bb, recon);

    finalize_k<<<1, 32>>>(scalars);
}

// round 11
// speedup vs baseline: 1.1448x; 1.1448x over previous
#include <cuda_runtime.h>
#include <math.h>

#define BATCH 32
#define SEQ   4096
#define NTOK  (BATCH*SEQ)      // 131072
#define AD    64
#define DCODE 256
#define KCODES 512

// ---------------- packed dual-fp32 FMA (bit-identical per-lane IEEE fma) ----
__device__ __forceinline__ void ffma2(float2& acc, float2 a, float2 b)
{
    unsigned long long A = *reinterpret_cast<unsigned long long*>(&a);
    unsigned long long B = *reinterpret_cast<unsigned long long*>(&b);
    unsigned long long C = *reinterpret_cast<unsigned long long*>(&acc);
    asm("fma.rn.f32x2 %0, %1, %2, %0;" : "+l"(C) : "l"(A), "l"(B));
    acc = *reinterpret_cast<float2*>(&C);
}

// ---------------- warp row-reduce for sum(x^2) (BIT-FROZEN since R7) --------
__device__ __forceinline__ float warp_sumsq_256(const float* __restrict__ row, int lane)
{
    float ax = 0.f, ay = 0.f;
#pragma unroll
    for (int i = 0; i < 4; i++) {
        float v0 = row[64*i + 2*lane + 0];
        float v1 = row[64*i + 2*lane + 1];
        ax = __fadd_rn(ax, __fmul_rn(v0, v0));
        ay = __fadd_rn(ay, __fmul_rn(v1, v1));
    }
    float s = __fadd_rn(ax, ay);
#pragma unroll
    for (int off = 16; off > 0; off >>= 1) {
        float o = __shfl_down_sync(0xffffffffu, s, off);
        s = __fadd_rn(s, o);
    }
    return s;   // valid in lane 0
}

// ---------------- scratch (__device__ globals: allocation-free) -------------
__device__ float g_bufA[NTOK*256];   // widest intermediate (z_e)
__device__ float g_bufB[NTOK*128];
__device__ float g_W_e0[BATCH*64*128];
__device__ float g_W_e1[BATCH*128*64];
__device__ float g_W_e2[BATCH*256*128];
__device__ float g_W_d0[BATCH*128*256];
__device__ float g_W_d1[BATCH*64*128];
__device__ float g_W_d2[BATCH*128*64];
__device__ int          g_idx[NTOK];
__device__ float        g_cnorm[KCODES];
__device__ unsigned int g_hist[KCODES];
__device__ double       g_sumsq;

// ---------------- stats reset (graph is replayed; must rezero) -------------
__global__ void zero_stats_k()
{
    int t = threadIdx.x;
    if (t < KCODES) g_hist[t] = 0u;
    if (t == 0)     g_sumsq = 0.0;
}

// ---------------- per-batch weight materialization (BIT-FROZEN since R3) ----
__global__ __launch_bounds__(256) void build_w_k(
    const float* __restrict__ bw, const float* __restrict__ aw,
    const float* __restrict__ ab, const float* __restrict__ adapt,
    float* __restrict__ Wout, int E)
{
    __shared__ float ad[BATCH*AD];
    for (int i = threadIdx.x; i < BATCH*AD; i += blockDim.x) ad[i] = adapt[i];
    __syncthreads();

    int e = blockIdx.x * blockDim.x + threadIdx.x;
    if (e >= E) return;

    float awr[AD];
#pragma unroll
    for (int d = 0; d < AD; d += 4) {
        float4 v = *reinterpret_cast<const float4*>(aw + (long)e*AD + d);
        awr[d] = v.x; awr[d+1] = v.y; awr[d+2] = v.z; awr[d+3] = v.w;
    }
    const float base = bw[e];
    const float abv  = ab[e];
    for (int b = 0; b < BATCH; b++) {
        float acc = 0.f;
#pragma unroll
        for (int d = 0; d < AD; d++) acc = fmaf(ad[b*AD + d], awr[d], acc);
        acc = __fadd_rn(acc, abv);
        Wout[(long)b*E + e] = __fadd_rn(base, acc);
    }
}

// ---------------- codebook squared norms (BIT-FROZEN since R7) --------------
__global__ __launch_bounds__(256) void cnorm_k(const float* __restrict__ CB)
{
    int warp = (blockIdx.x * blockDim.x + threadIdx.x) >> 5;  // = code index
    int lane = threadIdx.x & 31;
    if (warp < KCODES) {
        float s = warp_sumsq_256(CB + (long)warp * DCODE, lane);
        if (lane == 0) g_cnorm[warp] = s;
    }
}

// ---------------- liquid layer GEMM: double-buffered staging ----------------
// Arithmetic (ffma2 chains, k ascending, bias round) BIT-FROZEN; only the
// smem staging is pipelined.
template<int IN, int OUT, int ACT>
__global__ __launch_bounds__(256) void liquid_gemm_k(
    const float* __restrict__ X, const float* __restrict__ Wall,
    const float* __restrict__ bb, float* __restrict__ Y)
{
    const int b  = blockIdx.z;
    const int m0 = blockIdx.x * 64;
    const int n0 = blockIdx.y * 64;
    const float* Xb = X    + ((long)b*SEQ + m0) * IN;
    const float* Wb = Wall + (long)b*OUT*IN + (long)n0*IN;
    float*       Yb = Y    + ((long)b*SEQ + m0) * OUT + n0;

    __shared__ float As[2][16][68];
    __shared__ float Bs[2][16][68];

    const int tid  = threadIdx.x;
    const int lrow = tid >> 2;        // 0..63
    const int lk4  = (tid & 3) * 4;   // 0,4,8,12
    const int ty   = tid >> 4;        // 0..15 (m)
    const int tx   = tid & 15;        // 0..15 (n)

    float2 acc2[4][2];
#pragma unroll
    for (int i = 0; i < 4; i++) { acc2[i][0] = make_float2(0.f,0.f); acc2[i][1] = make_float2(0.f,0.f); }

    float4 av = *reinterpret_cast<const float4*>(Xb + (long)lrow*IN + lk4);
    float4 bv = *reinterpret_cast<const float4*>(Wb + (long)lrow*IN + lk4);

    int cur = 0;
    for (int k0 = 0; k0 < IN; k0 += 16) {
        As[cur][lk4+0][lrow] = av.x; As[cur][lk4+1][lrow] = av.y;
        As[cur][lk4+2][lrow] = av.z; As[cur][lk4+3][lrow] = av.w;
        Bs[cur][lk4+0][lrow] = bv.x; Bs[cur][lk4+1][lrow] = bv.y;
        Bs[cur][lk4+2][lrow] = bv.z; Bs[cur][lk4+3][lrow] = bv.w;
        __syncthreads();
        if (k0 + 16 < IN) {
            av = *reinterpret_cast<const float4*>(Xb + (long)lrow*IN + k0 + 16 + lk4);
            bv = *reinterpret_cast<const float4*>(Wb + (long)lrow*IN + k0 + 16 + lk4);
        }
#pragma unroll
        for (int k = 0; k < 16; k++) {
            float4 a = *reinterpret_cast<const float4*>(&As[cur][k][ty*4]);
            float4 q = *reinterpret_cast<const float4*>(&Bs[cur][k][tx*4]);
            float2 b0 = make_float2(q.x, q.y);
            float2 b1 = make_float2(q.z, q.w);
            float2 a0 = make_float2(a.x, a.x);
            float2 a1 = make_float2(a.y, a.y);
            float2 a2 = make_float2(a.z, a.z);
            float2 a3 = make_float2(a.w, a.w);
            ffma2(acc2[0][0], a0, b0); ffma2(acc2[0][1], a0, b1);
            ffma2(acc2[1][0], a1, b0); ffma2(acc2[1][1], a1, b1);
            ffma2(acc2[2][0], a2, b0); ffma2(acc2[2][1], a2, b1);
            ffma2(acc2[3][0], a3, b0); ffma2(acc2[3][1], a3, b1);
        }
        cur ^= 1;
    }

    float bias[4];
#pragma unroll
    for (int j = 0; j < 4; j++) bias[j] = bb[n0 + tx*4 + j];

#pragma unroll
    for (int i = 0; i < 4; i++) {
        const int m = ty*4 + i;
        float accv[4] = { acc2[i][0].x, acc2[i][0].y, acc2[i][1].x, acc2[i][1].y };
#pragma unroll
        for (int j = 0; j < 4; j++) {
            float v = __fadd_rn(accv[j], bias[j]);
            if (ACT == 1) v = fmaxf(v, 0.f);
            if (ACT == 2) v = 1.f / (1.f + expf(-v));
            Yb[(long)m*OUT + tx*4 + j] = v;
        }
    }
}

// ---------------- VQ argmin --------------------------------------------------
// Arithmetic BIT-FROZEN (R10 4-phase chains, fold ((c0+c1)+c2)+c3, score
// rounding, zn pattern). R11: Z staged TRANSPOSED (Zt[k][m]) so the 4 token
// values per k come from one broadcast LDS.128; B staging double-buffered
// with cross-tile prefetch.
__global__ __launch_bounds__(256) void vq_argmin_k(
    const float* __restrict__ Z, const float* __restrict__ CB)
{
    extern __shared__ float sm[];
    float (*Zt)[68]    = (float (*)[68])    sm;                         // 256 x 68
    float (*Bs)[16][68]= (float (*)[16][68])(sm + 256*68);              // 2 x 16 x 68
    float (*rv)[17]    = (float (*)[17])    (sm + 256*68 + 2*16*68);    // 64 x 17
    int   (*ri)[17]    = (int   (*)[17])    (sm + 256*68 + 2*16*68 + 64*17);
    float *zn_s        = (float*)           (sm + 256*68 + 2*16*68 + 64*17 + 64*17);

    const int m0  = blockIdx.x * 64;
    const int tid = threadIdx.x;

    // Per-token ||z||^2 from GLOBAL memory — identical values & op order.
    {
        const int warp = tid >> 5;
        const int lane = tid & 31;
        for (int j = 0; j < 8; j++) {
            int tok = warp * 8 + j;
            float s = warp_sumsq_256(Z + (long)(m0 + tok)*DCODE, lane);
            if (lane == 0) zn_s[tok] = s;
        }
    }

    // Stage Z transposed: Zt[k][m].
    for (int i = tid; i < 64*64; i += 256) {
        int m = i >> 6;
        int q = (i & 63) * 4;
        float4 v = *reinterpret_cast<const float4*>(Z + (long)(m0 + m)*DCODE + q);
        Zt[q+0][m] = v.x; Zt[q+1][m] = v.y; Zt[q+2][m] = v.z; Zt[q+3][m] = v.w;
    }
    __syncthreads();

    const int lrow = tid >> 2;
    const int lk4  = (tid & 3) * 4;
    const int ty   = tid >> 4;
    const int tx   = tid & 15;

    float zn[4];
#pragma unroll
    for (int i = 0; i < 4; i++) zn[i] = zn_s[ty*4 + i];

    float bestv[4];
    int   besti[4];
#pragma unroll
    for (int i = 0; i < 4; i++) { bestv[i] = 3.4e38f; besti[i] = 0; }

    int cur = 0;
    float4 bv = *reinterpret_cast<const float4*>(CB + (long)lrow*DCODE + lk4);  // n0=0,k0=0

    for (int n0 = 0; n0 < KCODES; n0 += 64) {
        float2 acc[4][4][2];   // [phase][i][h] — 4-phase chains (FROZEN)
#pragma unroll
        for (int p = 0; p < 4; p++)
#pragma unroll
            for (int i = 0; i < 4; i++) {
                acc[p][i][0] = make_float2(0.f,0.f);
                acc[p][i][1] = make_float2(0.f,0.f);
            }

        for (int k0 = 0; k0 < DCODE; k0 += 16) {
            Bs[cur][lk4+0][lrow] = bv.x; Bs[cur][lk4+1][lrow] = bv.y;
            Bs[cur][lk4+2][lrow] = bv.z; Bs[cur][lk4+3][lrow] = bv.w;
            __syncthreads();
            // Prefetch next 16-k block (cross n-tile at boundaries).
            {
                int nk = k0 + 16, nn = n0;
                if (nk == DCODE) { nk = 0; nn = n0 + 64; }
                if (nn < KCODES)
                    bv = *reinterpret_cast<const float4*>(
                        CB + (long)(nn + lrow)*DCODE + nk + lk4);
            }
#pragma unroll
            for (int k = 0; k < 16; k++) {
                const int p = k & 3;
                float4 a = *reinterpret_cast<const float4*>(&Zt[k0+k][ty*4]);
                float4 q = *reinterpret_cast<const float4*>(&Bs[cur][k][tx*4]);
                float2 b0 = make_float2(q.x, q.y);
                float2 b1 = make_float2(q.z, q.w);
                float2 a0 = make_float2(a.x, a.x);
                float2 a1 = make_float2(a.y, a.y);
                float2 a2 = make_float2(a.z, a.z);
                float2 a3 = make_float2(a.w, a.w);
                ffma2(acc[p][0][0], a0, b0); ffma2(acc[p][0][1], a0, b1);
                ffma2(acc[p][1][0], a1, b0); ffma2(acc[p][1][1], a1, b1);
                ffma2(acc[p][2][0], a2, b0); ffma2(acc[p][2][1], a2, b1);
                ffma2(acc[p][3][0], a3, b0); ffma2(acc[p][3][1], a3, b1);
            }
            cur ^= 1;
        }
#pragma unroll
        for (int j = 0; j < 4; j++) {
            const int code = n0 + tx*4 + j;
            const float cn = g_cnorm[code];
#pragma unroll
            for (int i = 0; i < 4; i++) {
                const int h = j >> 1;
                float c0 = (j & 1) ? acc[0][i][h].y : acc[0][i][h].x;
                float c1 = (j & 1) ? acc[1][i][h].y : acc[1][i][h].x;
                float c2 = (j & 1) ? acc[2][i][h].y : acc[2][i][h].x;
                float c3 = (j & 1) ? acc[3][i][h].y : acc[3][i][h].x;
                float dot = __fadd_rn(__fadd_rn(__fadd_rn(c0, c1), c2), c3);
                float t = __fadd_rn(zn[i], cn);                    // fl(zn + cn)
                float s = __fadd_rn(t, -__fmul_rn(2.f, dot));      // fl(t - 2*dot)
                if (s < bestv[i]) { bestv[i] = s; besti[i] = code; }
            }
        }
    }

    __syncthreads();
#pragma unroll
    for (int i = 0; i < 4; i++) {
        rv[ty*4 + i][tx] = bestv[i];
        ri[ty*4 + i][tx] = besti[i];
    }
    __syncthreads();

    if (tid < 64) {
        float bv2 = rv[tid][0]; int bi = ri[tid][0];
#pragma unroll
        for (int x = 1; x < 16; x++) {
            float v = rv[tid][x]; int ii = ri[tid][x];
            if (v < bv2 || (v == bv2 && ii < bi)) { bv2 = v; bi = ii; }
        }
        g_idx[m0 + tid] = bi;
    }
}

// ---------------- gather z_q (straight-through) + loss + histogram ----------
__global__ __launch_bounds__(256) void vq_gather_k(
    const float* __restrict__ Z, const float* __restrict__ CB,
    float* __restrict__ zq_out)
{
    __shared__ unsigned int hist_s[KCODES];
    __shared__ float ws[8];
    for (int i = threadIdx.x; i < KCODES; i += blockDim.x) hist_s[i] = 0u;
    __syncthreads();

    float lsum = 0.f;
    const int total  = NTOK * DCODE;
    const int stride = gridDim.x * blockDim.x;
    for (int e = blockIdx.x * blockDim.x + threadIdx.x; e < total; e += stride) {
        int token = e >> 8;
        int d     = e & 255;
        int idx   = g_idx[token];
        float q   = CB[(long)idx*DCODE + d];
        float z   = Z[e];
        float diff = __fadd_rn(q, -z);          // fl(q - z)
        lsum += diff * diff;
        zq_out[e] = __fadd_rn(z, diff);         // quantized_st = fl(z + fl(q - z))
        if (d == 0) atomicAdd(&hist_s[idx], 1u);
    }

#pragma unroll
    for (int o = 16; o > 0; o >>= 1) lsum += __shfl_xor_sync(0xffffffffu, lsum, o);
    if ((threadIdx.x & 31) == 0) ws[threadIdx.x >> 5] = lsum;
    __syncthreads();
    if (threadIdx.x == 0) {
        float s = 0.f;
#pragma unroll
        for (int w = 0; w < 8; w++) s += ws[w];
        atomicAdd(&g_sumsq, (double)s);
    }
    for (int i = threadIdx.x; i < KCODES; i += blockDim.x)
        if (hist_s[i]) atomicAdd(&g_hist[i], hist_s[i]);
}

// ---------------- scalars: vq_loss, perplexity ------------------------------
__global__ void finalize_k(float* __restrict__ scalars)
{
    if (threadIdx.x == 0 && blockIdx.x == 0) {
        double mse = g_sumsq / (double)((long)NTOK * DCODE);
        scalars[0] = (float)(mse * 1.25);
        double H = 0.0;
        for (int k = 0; k < KCODES; k++) {
            double p = (double)g_hist[k] / (double)NTOK;
            H -= p * log(p + 1e-10);
        }
        scalars[1] = (float)exp(H);
    }
}

// ---------------- launch --------------------------------------------------
static float* symaddr(const void* sym)
{
    void* p = nullptr;
    cudaGetSymbolAddress(&p, sym);
    return (float*)p;
}

extern "C" void kernel_launch(void* const* d_in, const int* in_sizes, int n_in,
                              void* d_out, int out_size)
{
    (void)in_sizes; (void)n_in; (void)out_size;

    const float* x        = (const float*)d_in[0];
    const float* adapt    = (const float*)d_in[1];
    const float* e0_bw = (const float*)d_in[2],  *e0_bb = (const float*)d_in[3],
               * e0_aw = (const float*)d_in[4],  *e0_ab = (const float*)d_in[5];
    const float* e1_bw = (const float*)d_in[6],  *e1_bb = (const float*)d_in[7],
               * e1_aw = (const float*)d_in[8],  *e1_ab = (const float*)d_in[9];
    const float* e2_bw = (const float*)d_in[10], *e2_bb = (const float*)d_in[11],
               * e2_aw = (const float*)d_in[12], *e2_ab = (const float*)d_in[13];
    const float* d0_bw = (const float*)d_in[14], *d0_bb = (const float*)d_in[15],
               * d0_aw = (const float*)d_in[16], *d0_ab = (const float*)d_in[17];
    const float* d1_bw = (const float*)d_in[18], *d1_bb = (const float*)d_in[19],
               * d1_aw = (const float*)d_in[20], *d1_ab = (const float*)d_in[21];
    const float* d2_bw = (const float*)d_in[22], *d2_bb = (const float*)d_in[23],
               * d2_aw = (const float*)d_in[24], *d2_ab = (const float*)d_in[25];
    const float* codebook = (const float*)d_in[26];

    float* out     = (float*)d_out;
    float* zq      = out;                       // [32,4096,256]
    float* scalars = out + (long)NTOK * DCODE;  // loss, perplexity
    float* recon   = scalars + 2;               // [32,4096,128]

    float* bufA = symaddr(g_bufA);
    float* bufB = symaddr(g_bufB);
    float* W_e0 = symaddr(g_W_e0);
    float* W_e1 = symaddr(g_W_e1);
    float* W_e2 = symaddr(g_W_e2);
    float* W_d0 = symaddr(g_W_d0);
    float* W_d1 = symaddr(g_W_d1);
    float* W_d2 = symaddr(g_W_d2);

    const dim3 blk(256);

    zero_stats_k<<<1, 512>>>();

    build_w_k<<<(64*128 + 255)/256, blk>>>(e0_bw, e0_aw, e0_ab, adapt, W_e0, 64*128);
    build_w_k<<<(128*64 + 255)/256, blk>>>(e1_bw, e1_aw, e1_ab, adapt, W_e1, 128*64);
    build_w_k<<<(256*128 + 255)/256, blk>>>(e2_bw, e2_aw, e2_ab, adapt, W_e2, 256*128);
    build_w_k<<<(128*256 + 255)/256, blk>>>(d0_bw, d0_aw, d0_ab, adapt, W_d0, 128*256);
    build_w_k<<<(64*128 + 255)/256, blk>>>(d1_bw, d1_aw, d1_ab, adapt, W_d1, 64*128);
    build_w_k<<<(128*64 + 255)/256, blk>>>(d2_bw, d2_aw, d2_ab, adapt, W_d2, 128*64);

    cnorm_k<<<64, blk>>>(codebook);   // 512 warps = 512 codes

    // encoder
    liquid_gemm_k<128,  64, 1><<<dim3(64, 1, BATCH), blk>>>(x,    W_e0, e0_bb, bufA);
    liquid_gemm_k< 64, 128, 1><<<dim3(64, 2, BATCH), blk>>>(bufA, W_e1, e1_bb, bufB);
    liquid_gemm_k<128, 256, 0><<<dim3(64, 4, BATCH), blk>>>(bufB, W_e2, e2_bb, bufA);

    // vector quantization
    const int vq_smem = (256*68 + 2*16*68 + 64*17 + 64*17 + 64) * (int)sizeof(float); // 87296 B
    cudaFuncSetAttribute(vq_argmin_k, cudaFuncAttributeMaxDynamicSharedMemorySize, vq_smem);
    vq_argmin_k<<<NTOK/64, blk, vq_smem>>>(bufA, codebook);
    vq_gather_k<<<1024, blk>>>(bufA, codebook, zq);

    // decoder
    liquid_gemm_k<256, 128, 1><<<dim3(64, 2, BATCH), blk>>>(zq,   W_d0, d0_bb, bufB);
    liquid_gemm_k<128,  64, 1><<<dim3(64, 1, BATCH), blk>>>(bufB, W_d1, d1_bb, bufA);
    liquid_gemm_k< 64, 128, 2><<<dim3(64, 2, BATCH), blk>>>(bufA, W_d2, d2_bb, recon);

    finalize_k<<<1, 32>>>(scalars);
}

// round 12
// speedup vs baseline: 1.2116x; 1.0583x over previous
#include <cuda_runtime.h>
#include <math.h>

#define BATCH 32
#define SEQ   4096
#define NTOK  (BATCH*SEQ)      // 131072
#define AD    64
#define DCODE 256
#define KCODES 512

// ---------------- packed dual-fp32 FMA (bit-identical per-lane IEEE fma) ----
__device__ __forceinline__ void ffma2(float2& acc, float2 a, float2 b)
{
    unsigned long long A = *reinterpret_cast<unsigned long long*>(&a);
    unsigned long long B = *reinterpret_cast<unsigned long long*>(&b);
    unsigned long long C = *reinterpret_cast<unsigned long long*>(&acc);
    asm("fma.rn.f32x2 %0, %1, %2, %0;" : "+l"(C) : "l"(A), "l"(B));
    acc = *reinterpret_cast<float2*>(&C);
}

// ---------------- warp row-reduce for sum(x^2) (BIT-FROZEN since R7) --------
__device__ __forceinline__ float warp_sumsq_256(const float* __restrict__ row, int lane)
{
    float ax = 0.f, ay = 0.f;
#pragma unroll
    for (int i = 0; i < 4; i++) {
        float v0 = row[64*i + 2*lane + 0];
        float v1 = row[64*i + 2*lane + 1];
        ax = __fadd_rn(ax, __fmul_rn(v0, v0));
        ay = __fadd_rn(ay, __fmul_rn(v1, v1));
    }
    float s = __fadd_rn(ax, ay);
#pragma unroll
    for (int off = 16; off > 0; off >>= 1) {
        float o = __shfl_down_sync(0xffffffffu, s, off);
        s = __fadd_rn(s, o);
    }
    return s;   // valid in lane 0
}

// ---------------- scratch (__device__ globals: allocation-free) -------------
__device__ float g_bufA[NTOK*256];   // widest intermediate (z_e)
__device__ float g_bufB[NTOK*128];
__device__ float g_W_e0[BATCH*64*128];
__device__ float g_W_e1[BATCH*128*64];
__device__ float g_W_e2[BATCH*256*128];
__device__ float g_W_d0[BATCH*128*256];
__device__ float g_W_d1[BATCH*64*128];
__device__ float g_W_d2[BATCH*128*64];
__device__ float        g_cnorm[KCODES];
__device__ unsigned int g_hist[KCODES];
__device__ double       g_sumsq;

// ---------------- codebook norms (FROZEN) + stats reset ---------------------
__global__ __launch_bounds__(256) void cnorm_k(const float* __restrict__ CB)
{
    if (blockIdx.x == 0) {                       // fold zero_stats here
        for (int i = threadIdx.x; i < KCODES; i += 256) g_hist[i] = 0u;
        if (threadIdx.x == 0) g_sumsq = 0.0;
    }
    int warp = (blockIdx.x * blockDim.x + threadIdx.x) >> 5;  // = code index
    int lane = threadIdx.x & 31;
    if (warp < KCODES) {
        float s = warp_sumsq_256(CB + (long)warp * DCODE, lane);
        if (lane == 0) g_cnorm[warp] = s;
    }
}

// ---------------- merged per-batch weight materialization -------------------
// Per-(b,e) arithmetic BIT-FROZEN (chain from 0, fmaf d ascending, +ab, +bw).
// One launch covers all 6 layers; batch loop split 4x for occupancy.
struct BWLayer { const float* bw; const float* aw; const float* ab; float* W; int E; };
struct BWAll   { BWLayer L[6]; int off[7]; };

__global__ __launch_bounds__(256) void build_w_all_k(BWAll P, const float* __restrict__ adapt)
{
    __shared__ float ad[BATCH*AD];
    for (int i = threadIdx.x; i < BATCH*AD; i += 256) ad[i] = adapt[i];
    __syncthreads();

    const int bgroup = blockIdx.x & 3;          // 8 batches per group
    const int ebid   = blockIdx.x >> 2;
    const int eg     = ebid * 256 + threadIdx.x;

    int layer = 0;
#pragma unroll
    for (int l = 0; l < 6; l++) if (eg >= P.off[l+1]) layer = l + 1;
    const BWLayer& L = P.L[layer];
    const int e = eg - P.off[layer];

    float awr[AD];
#pragma unroll
    for (int d = 0; d < AD; d += 4) {
        float4 v = *reinterpret_cast<const float4*>(L.aw + (long)e*AD + d);
        awr[d] = v.x; awr[d+1] = v.y; awr[d+2] = v.z; awr[d+3] = v.w;
    }
    const float base = L.bw[e];
    const float abv  = L.ab[e];
    for (int b = bgroup*8; b < bgroup*8 + 8; b++) {
        float acc = 0.f;
#pragma unroll
        for (int d = 0; d < AD; d++) acc = fmaf(ad[b*AD + d], awr[d], acc);
        acc = __fadd_rn(acc, abv);
        L.W[(long)b*L.E + e] = __fadd_rn(base, acc);
    }
}

// ---------------- liquid layer GEMM: 128x64 tile, double-buffered -----------
// Per-output arithmetic BIT-FROZEN (single ffma2 chain, k ascending, bias
// __fadd_rn). Only tiling/staging changed.
template<int IN, int OUT, int ACT>
__global__ __launch_bounds__(256) void liquid_gemm_k(
    const float* __restrict__ X, const float* __restrict__ Wall,
    const float* __restrict__ bb, float* __restrict__ Y)
{
    const int b  = blockIdx.z;
    const int m0 = blockIdx.x * 128;
    const int n0 = blockIdx.y * 64;
    const float* Xb = X    + ((long)b*SEQ + m0) * IN;
    const float* Wb = Wall + (long)b*OUT*IN + (long)n0*IN;
    float*       Yb = Y    + ((long)b*SEQ + m0) * OUT + n0;

    __shared__ float As[2][16][132];   // [k][m], 128 rows
    __shared__ float Bs[2][16][68];    // [k][n], 64 rows

    const int tid  = threadIdx.x;
    // A staging: 512 float4 -> 2 per thread
    const int ar0 = tid >> 1;                 // 0..127
    const int aq0 = (tid & 1) * 8;            // 0 or 8 (two float4: aq0, aq0+4)
    // B staging: 256 float4 -> 1 per thread
    const int br  = tid >> 2;                 // 0..63
    const int bq  = (tid & 3) * 4;
    const int ty  = tid >> 4;                 // 0..15 (m group of 8)
    const int tx  = tid & 15;                 // 0..15 (n group of 4)

    float2 acc2[8][2];
#pragma unroll
    for (int i = 0; i < 8; i++) { acc2[i][0] = make_float2(0.f,0.f); acc2[i][1] = make_float2(0.f,0.f); }

    float4 av0 = *reinterpret_cast<const float4*>(Xb + (long)ar0*IN + aq0);
    float4 av1 = *reinterpret_cast<const float4*>(Xb + (long)ar0*IN + aq0 + 4);
    float4 bv  = *reinterpret_cast<const float4*>(Wb + (long)br*IN + bq);

    int cur = 0;
    for (int k0 = 0; k0 < IN; k0 += 16) {
        As[cur][aq0+0][ar0] = av0.x; As[cur][aq0+1][ar0] = av0.y;
        As[cur][aq0+2][ar0] = av0.z; As[cur][aq0+3][ar0] = av0.w;
        As[cur][aq0+4][ar0] = av1.x; As[cur][aq0+5][ar0] = av1.y;
        As[cur][aq0+6][ar0] = av1.z; As[cur][aq0+7][ar0] = av1.w;
        Bs[cur][bq+0][br] = bv.x; Bs[cur][bq+1][br] = bv.y;
        Bs[cur][bq+2][br] = bv.z; Bs[cur][bq+3][br] = bv.w;
        __syncthreads();
        if (k0 + 16 < IN) {
            av0 = *reinterpret_cast<const float4*>(Xb + (long)ar0*IN + k0 + 16 + aq0);
            av1 = *reinterpret_cast<const float4*>(Xb + (long)ar0*IN + k0 + 16 + aq0 + 4);
            bv  = *reinterpret_cast<const float4*>(Wb + (long)br*IN + k0 + 16 + bq);
        }
#pragma unroll
        for (int k = 0; k < 16; k++) {
            float4 alo = *reinterpret_cast<const float4*>(&As[cur][k][ty*8]);
            float4 ahi = *reinterpret_cast<const float4*>(&As[cur][k][ty*8+4]);
            float4 q   = *reinterpret_cast<const float4*>(&Bs[cur][k][tx*4]);
            float2 b0 = make_float2(q.x, q.y);
            float2 b1 = make_float2(q.z, q.w);
            float am[8] = {alo.x, alo.y, alo.z, alo.w, ahi.x, ahi.y, ahi.z, ahi.w};
#pragma unroll
            for (int i = 0; i < 8; i++) {
                float2 ai = make_float2(am[i], am[i]);
                ffma2(acc2[i][0], ai, b0);
                ffma2(acc2[i][1], ai, b1);
            }
        }
        cur ^= 1;
    }

    float bias[4];
#pragma unroll
    for (int j = 0; j < 4; j++) bias[j] = bb[n0 + tx*4 + j];

#pragma unroll
    for (int i = 0; i < 8; i++) {
        const int m = ty*8 + i;
        float accv[4] = { acc2[i][0].x, acc2[i][0].y, acc2[i][1].x, acc2[i][1].y };
#pragma unroll
        for (int j = 0; j < 4; j++) {
            float v = __fadd_rn(accv[j], bias[j]);
            if (ACT == 1) v = fmaxf(v, 0.f);
            if (ACT == 2) v = 1.f / (1.f + expf(-v));
            Yb[(long)m*OUT + tx*4 + j] = v;
        }
    }
}

// ---------------- VQ argmin + fused gather/loss/hist -------------------------
// Argmin arithmetic BIT-FROZEN (R10 4-phase chains, fold ((c0+c1)+c2)+c3,
// score rounding, zn pattern, first-index ties). R12: gather fused into
// epilogue (z from Zt, q from CB; same element formulas).
__global__ __launch_bounds__(256) void vq_argmin_k(
    const float* __restrict__ Z, const float* __restrict__ CB,
    float* __restrict__ zq_out)
{
    extern __shared__ float sm[];
    float (*Zt)[68]    = (float (*)[68])    sm;                         // 256 x 68
    float (*Bs)[16][68]= (float (*)[16][68])(sm + 256*68);              // 2 x 16 x 68
    float (*rv)[17]    = (float (*)[17])    (sm + 256*68 + 2*16*68);    // 64 x 17
    int   (*ri)[17]    = (int   (*)[17])    (sm + 256*68 + 2*16*68 + 64*17);
    float *zn_s        = (float*)           (sm + 256*68 + 2*16*68 + 64*17 + 64*17);
    int   *idx_s       = (int*)             (sm + 256*68 + 2*16*68 + 64*17 + 64*17 + 64);
    float *ws          = (float*)           (sm + 256*68 + 2*16*68 + 64*17 + 64*17 + 64 + 64);

    const int m0  = blockIdx.x * 64;
    const int tid = threadIdx.x;

    // Per-token ||z||^2 from GLOBAL memory — FROZEN values & op order.
    {
        const int warp = tid >> 5;
        const int lane = tid & 31;
        for (int j = 0; j < 8; j++) {
            int tok = warp * 8 + j;
            float s = warp_sumsq_256(Z + (long)(m0 + tok)*DCODE, lane);
            if (lane == 0) zn_s[tok] = s;
        }
    }

    // Stage Z transposed: Zt[k][m].
    for (int i = tid; i < 64*64; i += 256) {
        int m = i >> 6;
        int q = (i & 63) * 4;
        float4 v = *reinterpret_cast<const float4*>(Z + (long)(m0 + m)*DCODE + q);
        Zt[q+0][m] = v.x; Zt[q+1][m] = v.y; Zt[q+2][m] = v.z; Zt[q+3][m] = v.w;
    }
    __syncthreads();

    const int lrow = tid >> 2;
    const int lk4  = (tid & 3) * 4;
    const int ty   = tid >> 4;
    const int tx   = tid & 15;

    float zn[4];
#pragma unroll
    for (int i = 0; i < 4; i++) zn[i] = zn_s[ty*4 + i];

    float bestv[4];
    int   besti[4];
#pragma unroll
    for (int i = 0; i < 4; i++) { bestv[i] = 3.4e38f; besti[i] = 0; }

    int cur = 0;
    float4 pb = *reinterpret_cast<const float4*>(CB + (long)lrow*DCODE + lk4);  // n0=0,k0=0

    for (int n0 = 0; n0 < KCODES; n0 += 64) {
        float2 acc[4][4][2];   // [phase][i][h] — 4-phase chains (FROZEN)
#pragma unroll
        for (int p = 0; p < 4; p++)
#pragma unroll
            for (int i = 0; i < 4; i++) {
                acc[p][i][0] = make_float2(0.f,0.f);
                acc[p][i][1] = make_float2(0.f,0.f);
            }

        for (int k0 = 0; k0 < DCODE; k0 += 16) {
            Bs[cur][lk4+0][lrow] = pb.x; Bs[cur][lk4+1][lrow] = pb.y;
            Bs[cur][lk4+2][lrow] = pb.z; Bs[cur][lk4+3][lrow] = pb.w;
            __syncthreads();
            {
                int nk = k0 + 16, nn = n0;
                if (nk == DCODE) { nk = 0; nn = n0 + 64; }
                if (nn < KCODES)
                    pb = *reinterpret_cast<const float4*>(
                        CB + (long)(nn + lrow)*DCODE + nk + lk4);
            }
#pragma unroll
            for (int k = 0; k < 16; k++) {
                const int p = k & 3;
                float4 a = *reinterpret_cast<const float4*>(&Zt[k0+k][ty*4]);
                float4 q = *reinterpret_cast<const float4*>(&Bs[cur][k][tx*4]);
                float2 b0 = make_float2(q.x, q.y);
                float2 b1 = make_float2(q.z, q.w);
                float2 a0 = make_float2(a.x, a.x);
                float2 a1 = make_float2(a.y, a.y);
                float2 a2 = make_float2(a.z, a.z);
                float2 a3 = make_float2(a.w, a.w);
                ffma2(acc[p][0][0], a0, b0); ffma2(acc[p][0][1], a0, b1);
                ffma2(acc[p][1][0], a1, b0); ffma2(acc[p][1][1], a1, b1);
                ffma2(acc[p][2][0], a2, b0); ffma2(acc[p][2][1], a2, b1);
                ffma2(acc[p][3][0], a3, b0); ffma2(acc[p][3][1], a3, b1);
            }
            cur ^= 1;
        }
#pragma unroll
        for (int j = 0; j < 4; j++) {
            const int code = n0 + tx*4 + j;
            const float cn = g_cnorm[code];
#pragma unroll
            for (int i = 0; i < 4; i++) {
                const int h = j >> 1;
                float c0 = (j & 1) ? acc[0][i][h].y : acc[0][i][h].x;
                float c1 = (j & 1) ? acc[1][i][h].y : acc[1][i][h].x;
                float c2 = (j & 1) ? acc[2][i][h].y : acc[2][i][h].x;
                float c3 = (j & 1) ? acc[3][i][h].y : acc[3][i][h].x;
                float dot = __fadd_rn(__fadd_rn(__fadd_rn(c0, c1), c2), c3);
                float t = __fadd_rn(zn[i], cn);                    // fl(zn + cn)
                float s = __fadd_rn(t, -__fmul_rn(2.f, dot));      // fl(t - 2*dot)
                if (s < bestv[i]) { bestv[i] = s; besti[i] = code; }
            }
        }
    }

    __syncthreads();
#pragma unroll
    for (int i = 0; i < 4; i++) {
        rv[ty*4 + i][tx] = bestv[i];
        ri[ty*4 + i][tx] = besti[i];
    }
    __syncthreads();

    if (tid < 64) {
        float bv2 = rv[tid][0]; int bi = ri[tid][0];
#pragma unroll
        for (int x = 1; x < 16; x++) {
            float v = rv[tid][x]; int ii = ri[tid][x];
            if (v < bv2 || (v == bv2 && ii < bi)) { bv2 = v; bi = ii; }
        }
        idx_s[tid] = bi;
    }
    __syncthreads();

    // -------- fused gather: z_q (straight-through), loss, histogram --------
    float lsum = 0.f;
    for (int i = 0; i < 64; i++) {
        int idx  = idx_s[i];
        float q  = CB[(long)idx*DCODE + tid];   // coalesced row
        float z  = Zt[tid][i];
        float diff = __fadd_rn(q, -z);          // fl(q - z)       (FROZEN)
        lsum += diff * diff;
        zq_out[(long)(m0 + i)*DCODE + tid] = __fadd_rn(z, diff);   // (FROZEN)
    }
#pragma unroll
    for (int o = 16; o > 0; o >>= 1) lsum += __shfl_xor_sync(0xffffffffu, lsum, o);
    if ((tid & 31) == 0) ws[tid >> 5] = lsum;
    __syncthreads();
    if (tid == 0) {
        float s = 0.f;
#pragma unroll
        for (int w = 0; w < 8; w++) s += ws[w];
        atomicAdd(&g_sumsq, (double)s);
    }
    if (tid < 64) atomicAdd(&g_hist[idx_s[tid]], 1u);
}

// ---------------- scalars: vq_loss, perplexity ------------------------------
__global__ void finalize_k(float* __restrict__ scalars)
{
    if (threadIdx.x == 0 && blockIdx.x == 0) {
        double mse = g_sumsq / (double)((long)NTOK * DCODE);
        scalars[0] = (float)(mse * 1.25);
        double H = 0.0;
        for (int k = 0; k < KCODES; k++) {
            double p = (double)g_hist[k] / (double)NTOK;
            H -= p * log(p + 1e-10);
        }
        scalars[1] = (float)exp(H);
    }
}

// ---------------- launch --------------------------------------------------
static float* symaddr(const void* sym)
{
    void* p = nullptr;
    cudaGetSymbolAddress(&p, sym);
    return (float*)p;
}

extern "C" void kernel_launch(void* const* d_in, const int* in_sizes, int n_in,
                              void* d_out, int out_size)
{
    (void)in_sizes; (void)n_in; (void)out_size;

    const float* x        = (const float*)d_in[0];
    const float* adapt    = (const float*)d_in[1];
    const float* e0_bw = (const float*)d_in[2],  *e0_bb = (const float*)d_in[3],
               * e0_aw = (const float*)d_in[4],  *e0_ab = (const float*)d_in[5];
    const float* e1_bw = (const float*)d_in[6],  *e1_bb = (const float*)d_in[7],
               * e1_aw = (const float*)d_in[8],  *e1_ab = (const float*)d_in[9];
    const float* e2_bw = (const float*)d_in[10], *e2_bb = (const float*)d_in[11],
               * e2_aw = (const float*)d_in[12], *e2_ab = (const float*)d_in[13];
    const float* d0_bw = (const float*)d_in[14], *d0_bb = (const float*)d_in[15],
               * d0_aw = (const float*)d_in[16], *d0_ab = (const float*)d_in[17];
    const float* d1_bw = (const float*)d_in[18], *d1_bb = (const float*)d_in[19],
               * d1_aw = (const float*)d_in[20], *d1_ab = (const float*)d_in[21];
    const float* d2_bw = (const float*)d_in[22], *d2_bb = (const float*)d_in[23],
               * d2_aw = (const float*)d_in[24], *d2_ab = (const float*)d_in[25];
    const float* codebook = (const float*)d_in[26];

    float* out     = (float*)d_out;
    float* zq      = out;                       // [32,4096,256]
    float* scalars = out + (long)NTOK * DCODE;  // loss, perplexity
    float* recon   = scalars + 2;               // [32,4096,128]

    float* bufA = symaddr(g_bufA);
    float* bufB = symaddr(g_bufB);
    float* W_e0 = symaddr(g_W_e0);
    float* W_e1 = symaddr(g_W_e1);
    float* W_e2 = symaddr(g_W_e2);
    float* W_d0 = symaddr(g_W_d0);
    float* W_d1 = symaddr(g_W_d1);
    float* W_d2 = symaddr(g_W_d2);

    const dim3 blk(256);

    cnorm_k<<<64, blk>>>(codebook);   // includes stats reset (block 0)

    BWAll P;
    P.L[0] = { e0_bw, e0_aw, e0_ab, W_e0, 64*128 };
    P.L[1] = { e1_bw, e1_aw, e1_ab, W_e1, 128*64 };
    P.L[2] = { e2_bw, e2_aw, e2_ab, W_e2, 256*128 };
    P.L[3] = { d0_bw, d0_aw, d0_ab, W_d0, 128*256 };
    P.L[4] = { d1_bw, d1_aw, d1_ab, W_d1, 64*128 };
    P.L[5] = { d2_bw, d2_aw, d2_ab, W_d2, 128*64 };
    P.off[0] = 0;
    for (int l = 0; l < 6; l++) P.off[l+1] = P.off[l] + P.L[l].E;
    build_w_all_k<<<(98304/256)*4, blk>>>(P, adapt);

    // encoder
    liquid_gemm_k<128,  64, 1><<<dim3(32, 1, BATCH), blk>>>(x,    W_e0, e0_bb, bufA);
    liquid_gemm_k< 64, 128, 1><<<dim3(32, 2, BATCH), blk>>>(bufA, W_e1, e1_bb, bufB);
    liquid_gemm_k<128, 256, 0><<<dim3(32, 4, BATCH), blk>>>(bufB, W_e2, e2_bb, bufA);

    // vector quantization (argmin + fused gather/loss/hist)
    const int vq_smem = (256*68 + 2*16*68 + 64*17 + 64*17 + 64 + 64 + 8) * (int)sizeof(float);
    cudaFuncSetAttribute(vq_argmin_k, cudaFuncAttributeMaxDynamicSharedMemorySize, vq_smem);
    vq_argmin_k<<<NTOK/64, blk, vq_smem>>>(bufA, codebook, zq);

    // decoder
    liquid_gemm_k<256, 128, 1><<<dim3(32, 2, BATCH), blk>>>(zq,   W_d0, d0_bb, bufB);
    liquid_gemm_k<128,  64, 1><<<dim3(32, 1, BATCH), blk>>>(bufB, W_d1, d1_bb, bufA);
    liquid_gemm_k< 64, 128, 2><<<dim3(32, 2, BATCH), blk>>>(bufA, W_d2, d2_bb, recon);

    finalize_k<<<1, 32>>>(scalars);
}